// round 13
// baseline (speedup 1.0000x reference)
#include <cuda_runtime.h>
#include <math.h>

// ---------------------------------------------------------------------------
// Problem constants
// ---------------------------------------------------------------------------
#define N_TOK   8192          // B*T = 4*2048
#define D_DIM   1024
#define E_NUM   8
#define K_TOP   2
#define CAP     2048          // ceil(2.0 * 8192 / 8)
#define HID_DIM 4096

// ---------------------------------------------------------------------------
// Scratch (device globals: allocation-free rule). Zero-initialized at load;
// unwritten dispatch slots stay zero across calls (writes are deterministic).
// ---------------------------------------------------------------------------
__device__ __align__(16) float g_disp[(size_t)E_NUM * CAP * D_DIM];     //  64 MB
__device__ __align__(16) float g_h   [(size_t)E_NUM * CAP * HID_DIM];   // 256 MB
__device__ __align__(16) float g_oute[(size_t)E_NUM * CAP * D_DIM];     //  64 MB
__device__ int   g_top_e[N_TOK * K_TOP];
__device__ float g_top_p[N_TOK * K_TOP];
__device__ int   g_dest [N_TOK * K_TOP];

// ---------------------------------------------------------------------------
// Helpers
// ---------------------------------------------------------------------------
__device__ __forceinline__ float to_tf32(float x) {
    unsigned int u;
    asm("cvt.rna.tf32.f32 %0, %1;" : "=r"(u) : "f"(x));
    return __uint_as_float(u);
}

__device__ __forceinline__ float gelu_f(float v) {
    // exact (erf-based) gelu, matches jax approximate=False
    return 0.5f * v * (1.0f + erff(v * 0.7071067811865476f));
}

__device__ __forceinline__ int swz(int k) {  // k in [0,32)
    return ((k & 3) << 3) ^ ((k >> 2) << 2);
}

__device__ __forceinline__ void mma_tf32(float (&c)[4],
                                         const unsigned int (&a)[4],
                                         const unsigned int (&b)[2]) {
    asm volatile(
        "mma.sync.aligned.m16n8k8.row.col.f32.tf32.tf32.f32 "
        "{%0,%1,%2,%3}, {%4,%5,%6,%7}, {%8,%9}, {%0,%1,%2,%3};\n"
        : "+f"(c[0]), "+f"(c[1]), "+f"(c[2]), "+f"(c[3])
        : "r"(a[0]), "r"(a[1]), "r"(a[2]), "r"(a[3]),
          "r"(b[0]), "r"(b[1]));
}

// ---------------------------------------------------------------------------
// 1) Router: logits = x @ gate_w; softmax; top-2 (tie -> lower index)
//    one warp per token, 8 tokens per block
// ---------------------------------------------------------------------------
__global__ void __launch_bounds__(256) router_kernel(const float* __restrict__ x,
                                                     const float* __restrict__ gw) {
    __shared__ float sgw[E_NUM * D_DIM];   // transposed [e][d], 32 KB
    const int tid = threadIdx.x;
    for (int f = tid; f < E_NUM * D_DIM; f += 256) {
        int d = f >> 3, e = f & 7;
        sgw[e * D_DIM + d] = gw[f];        // gw[d*8+e]
    }
    __syncthreads();

    const int lane = tid & 31;
    const int n = blockIdx.x * 8 + (tid >> 5);
    const float* xr = x + (size_t)n * D_DIM;

    float acc[8];
#pragma unroll
    for (int e = 0; e < 8; e++) acc[e] = 0.f;
    for (int i = 0; i < 32; i++) {
        int d = i * 32 + lane;
        float xv = xr[d];
#pragma unroll
        for (int e = 0; e < 8; e++) acc[e] += xv * sgw[e * D_DIM + d];
    }
#pragma unroll
    for (int e = 0; e < 8; e++)
#pragma unroll
        for (int o = 16; o > 0; o >>= 1) acc[e] += __shfl_xor_sync(0xffffffffu, acc[e], o);

    if (lane == 0) {
        int b1 = 0;
        for (int e = 1; e < 8; e++) if (acc[e] > acc[b1]) b1 = e;
        int b2 = (b1 == 0) ? 1 : 0;
        for (int e = 0; e < 8; e++) if (e != b1 && acc[e] > acc[b2]) b2 = e;

        float mx = acc[0];
        for (int e = 1; e < 8; e++) mx = fmaxf(mx, acc[e]);
        float ex[8], s = 0.f;
        for (int e = 0; e < 8; e++) { ex[e] = expf(acc[e] - mx); s += ex[e]; }
        float inv = 1.0f / s;

        g_top_e[2 * n]     = b1;
        g_top_e[2 * n + 1] = b2;
        g_top_p[2 * n]     = ex[b1] * inv;
        g_top_p[2 * n + 1] = ex[b2] * inv;
    }
}

// ---------------------------------------------------------------------------
// 2) Ordered capacity scan (single block): per-expert exclusive cumsum over
//    tokens in index order; keep = position < CAP
// ---------------------------------------------------------------------------
__global__ void __launch_bounds__(256) scan_kernel() {
    __shared__ int scnt[256][8];
    const int tid = threadIdx.x;
    const int base = tid * 32;   // 32 tokens per thread

    int cnt[8];
#pragma unroll
    for (int e = 0; e < 8; e++) cnt[e] = 0;
    for (int t = 0; t < 32; t++) {
        int n = base + t;
        cnt[g_top_e[2 * n]]++;
        cnt[g_top_e[2 * n + 1]]++;
    }
#pragma unroll
    for (int e = 0; e < 8; e++) scnt[tid][e] = cnt[e];
    __syncthreads();

    if (tid < 8) {   // serial exclusive scan per expert (tiny)
        int run = 0;
        for (int i = 0; i < 256; i++) {
            int v = scnt[i][tid];
            scnt[i][tid] = run;
            run += v;
        }
    }
    __syncthreads();

    int off[8];
#pragma unroll
    for (int e = 0; e < 8; e++) off[e] = scnt[tid][e];
    for (int t = 0; t < 32; t++) {
        int n = base + t;
        for (int k = 0; k < 2; k++) {
            int e = g_top_e[2 * n + k];
            int p = off[e]++;
            g_dest[2 * n + k] = (p < CAP) ? (e * CAP + p) : -1;
        }
    }
}

// ---------------------------------------------------------------------------
// 3) Dispatch: scatter token rows into per-expert capacity buffers
// ---------------------------------------------------------------------------
__global__ void __launch_bounds__(256) dispatch_kernel(const float* __restrict__ x) {
    const int idx = blockIdx.x;
    const int dst = g_dest[idx];
    if (dst < 0) return;
    const int n = idx >> 1;
    const float4* src = reinterpret_cast<const float4*>(x + (size_t)n * D_DIM);
    float4* d = reinterpret_cast<float4*>(g_disp + (size_t)dst * D_DIM);
    d[threadIdx.x] = src[threadIdx.x];      // 256 * float4 = 1024 floats
}

// ---------------------------------------------------------------------------
// 4) Grouped GEMM: C[e] = A[e] @ B[e] + bias[e], optional exact GELU.
//    A: [E][M][K] (K contig), B: [E][K][N] (N contig), C: [E][M][N].
//    128x128x32 tile, 8 warps (4Mx2N), tf32 mma m16n8k8,
//    XOR-swizzled smem, double-buffered gmem->reg->smem pipeline.
// ---------------------------------------------------------------------------
template <bool GELU>
__global__ void __launch_bounds__(256, 1)
gemm_kernel(const float* __restrict__ A, const float* __restrict__ B,
            const float* __restrict__ bias, float* __restrict__ C,
            int Mtot, int Ktot, int Ntot) {
    extern __shared__ float sm[];
    float* AsBuf = sm;            // [2][32*128]
    float* BsBuf = sm + 8192;     // [2][32*128]

    const int tid  = threadIdx.x;
    const int lane = tid & 31;
    const int warp = tid >> 5;
    const int wm   = warp >> 1;   // 0..3
    const int wn   = warp & 1;    // 0..1

    const int e  = blockIdx.z;
    const int m0 = blockIdx.y << 7;
    const int n0 = blockIdx.x << 7;

    const float* Ag = A + (size_t)e * Mtot * Ktot
                        + (size_t)(m0 + (tid >> 3)) * Ktot + ((tid & 7) << 2);
    const float* Bg = B + (size_t)e * Ktot * Ntot
                        + (size_t)(tid >> 5) * Ntot + n0 + ((tid & 31) << 2);

    const int nk = Ktot >> 5;

    float4 ar[4], br[4];
    float  c[2][8][4];
#pragma unroll
    for (int i = 0; i < 2; i++)
#pragma unroll
        for (int j = 0; j < 8; j++)
#pragma unroll
            for (int q = 0; q < 4; q++) c[i][j][q] = 0.f;

    auto LDG = [&](int kb) {
        const float* ap = Ag + (kb << 5);
        const float* bp = Bg + (size_t)(kb << 5) * Ntot;
#pragma unroll
        for (int i = 0; i < 4; i++) {
            ar[i] = *reinterpret_cast<const float4*>(ap + (size_t)(i << 5) * Ktot);
            br[i] = *reinterpret_cast<const float4*>(bp + (size_t)(i << 3) * Ntot);
        }
    };

    auto STS = [&](int buf) {
        float* As = AsBuf + (buf << 12);
        float* Bs = BsBuf + (buf << 12);
#pragma unroll
        for (int i = 0; i < 4; i++) {
            // A: transpose into [k][m] swizzled
            const int m  = (tid >> 3) + (i << 5);
            const int k4 = (tid & 7) << 2;
            float v[4] = {ar[i].x, ar[i].y, ar[i].z, ar[i].w};
#pragma unroll
            for (int j = 0; j < 4; j++) {
                int k = k4 + j;
                As[(k << 7) + (m ^ swz(k))] = to_tf32(v[j]);
            }
            // B: [k][n] swizzled (swz is multiple of 4 -> float4 stays intact)
            const int bk = (tid >> 5) + (i << 3);
            const int bn = (tid & 31) << 2;
            float4* p = reinterpret_cast<float4*>(&Bs[(bk << 7) + (bn ^ swz(bk))]);
            *p = make_float4(to_tf32(br[i].x), to_tf32(br[i].y),
                             to_tf32(br[i].z), to_tf32(br[i].w));
        }
    };

    auto COMPUTE = [&](int buf) {
        const unsigned int* As = reinterpret_cast<const unsigned int*>(AsBuf + (buf << 12));
        const unsigned int* Bs = reinterpret_cast<const unsigned int*>(BsBuf + (buf << 12));
        const int c4 = lane & 3, g = lane >> 2;
#pragma unroll
        for (int kk = 0; kk < 4; kk++) {
            const int klo = (kk << 3) + c4;
            const int khi = klo + 4;
            const int slo = swz(klo), shi = swz(khi);
            unsigned int af[2][4];
#pragma unroll
            for (int im = 0; im < 2; im++) {
                const int mb = (wm << 5) + (im << 4) + g;
                af[im][0] = As[(klo << 7) + (mb ^ slo)];
                af[im][1] = As[(klo << 7) + ((mb + 8) ^ slo)];
                af[im][2] = As[(khi << 7) + (mb ^ shi)];
                af[im][3] = As[(khi << 7) + ((mb + 8) ^ shi)];
            }
            unsigned int bf[8][2];
#pragma unroll
            for (int jn = 0; jn < 8; jn++) {
                const int nb = (wn << 6) + (jn << 3) + g;
                bf[jn][0] = Bs[(klo << 7) + (nb ^ slo)];
                bf[jn][1] = Bs[(khi << 7) + (nb ^ shi)];
            }
#pragma unroll
            for (int im = 0; im < 2; im++)
#pragma unroll
                for (int jn = 0; jn < 8; jn++)
                    mma_tf32(c[im][jn], af[im], bf[jn]);
        }
    };

    LDG(0);
    STS(0);
    __syncthreads();
    int cur = 0;
    for (int kb = 0; kb < nk; kb++) {
        const bool more = (kb + 1 < nk);
        if (more) LDG(kb + 1);
        COMPUTE(cur);
        if (more) STS(cur ^ 1);
        __syncthreads();
        cur ^= 1;
    }

    // epilogue: bias (+gelu), fp32 store
    float* Cg = C + (size_t)e * Mtot * Ntot + (size_t)m0 * Ntot + n0;
    const float* bg = bias + (size_t)e * Ntot + n0;
#pragma unroll
    for (int im = 0; im < 2; im++) {
        const int r = (wm << 5) + (im << 4) + (lane >> 2);
#pragma unroll
        for (int jn = 0; jn < 8; jn++) {
            const int cc = (wn << 6) + (jn << 3) + ((lane & 3) << 1);
            const float b0 = bg[cc], b1v = bg[cc + 1];
            float v0 = c[im][jn][0] + b0;
            float v1 = c[im][jn][1] + b1v;
            float v2 = c[im][jn][2] + b0;
            float v3 = c[im][jn][3] + b1v;
            if (GELU) { v0 = gelu_f(v0); v1 = gelu_f(v1); v2 = gelu_f(v2); v3 = gelu_f(v3); }
            *reinterpret_cast<float2*>(&Cg[(size_t)r * Ntot + cc])       = make_float2(v0, v1);
            *reinterpret_cast<float2*>(&Cg[(size_t)(r + 8) * Ntot + cc]) = make_float2(v2, v3);
        }
    }
}

// ---------------------------------------------------------------------------
// 5) Combine: out[n] = sum_k gate_k * out_e[slot_k]   (dropped -> weight 0)
// ---------------------------------------------------------------------------
__global__ void __launch_bounds__(256) combine_kernel(float* __restrict__ out) {
    const int n = blockIdx.x;
    const int t = threadIdx.x;   // 256 threads * float4 = 1024 floats
    const int d0 = g_dest[2 * n], d1 = g_dest[2 * n + 1];
    float4 acc = make_float4(0.f, 0.f, 0.f, 0.f);
    if (d0 >= 0) {
        const float w = g_top_p[2 * n];
        float4 v = reinterpret_cast<const float4*>(g_oute + (size_t)d0 * D_DIM)[t];
        acc.x = w * v.x; acc.y = w * v.y; acc.z = w * v.z; acc.w = w * v.w;
    }
    if (d1 >= 0) {
        const float w = g_top_p[2 * n + 1];
        float4 v = reinterpret_cast<const float4*>(g_oute + (size_t)d1 * D_DIM)[t];
        acc.x += w * v.x; acc.y += w * v.y; acc.z += w * v.z; acc.w += w * v.w;
    }
    reinterpret_cast<float4*>(out + (size_t)n * D_DIM)[t] = acc;
}

// aux_loss = 0 (eval mode) + any tail padding in d_out
__global__ void tail_zero_kernel(float* __restrict__ p, int n) {
    int i = blockIdx.x * blockDim.x + threadIdx.x;
    if (i < n) p[i] = 0.f;
}

// ---------------------------------------------------------------------------
// Launch
// ---------------------------------------------------------------------------
extern "C" void kernel_launch(void* const* d_in, const int* in_sizes, int n_in,
                              void* d_out, int out_size) {
    const float* x  = (const float*)d_in[0];   // (4,2048,1024)
    const float* gw = (const float*)d_in[1];   // (1024,8)
    const float* w1 = (const float*)d_in[2];   // (8,1024,4096)
    const float* b1 = (const float*)d_in[3];   // (8,4096)
    const float* w2 = (const float*)d_in[4];   // (8,4096,1024)
    const float* b2 = (const float*)d_in[5];   // (8,1024)
    float* out = (float*)d_out;

    float *disp, *h, *oute;
    cudaGetSymbolAddress((void**)&disp, g_disp);
    cudaGetSymbolAddress((void**)&h,    g_h);
    cudaGetSymbolAddress((void**)&oute, g_oute);

    cudaFuncSetAttribute((const void*)gemm_kernel<true>,
                         cudaFuncAttributeMaxDynamicSharedMemorySize, 65536);
    cudaFuncSetAttribute((const void*)gemm_kernel<false>,
                         cudaFuncAttributeMaxDynamicSharedMemorySize, 65536);

    router_kernel<<<N_TOK / 8, 256>>>(x, gw);
    scan_kernel<<<1, 256>>>();
    dispatch_kernel<<<N_TOK * K_TOP, 256>>>(x);

    gemm_kernel<true><<<dim3(HID_DIM / 128, CAP / 128, E_NUM), 256, 65536>>>(
        disp, w1, b1, h, CAP, D_DIM, HID_DIM);
    gemm_kernel<false><<<dim3(D_DIM / 128, CAP / 128, E_NUM), 256, 65536>>>(
        h, w2, b2, oute, CAP, HID_DIM, D_DIM);

    combine_kernel<<<N_TOK, 256>>>(out);

    const int tail = out_size - N_TOK * D_DIM;
    if (tail > 0)
        tail_zero_kernel<<<(tail + 255) / 256, 256>>>(out + (size_t)N_TOK * D_DIM, tail);
}